// round 10
// baseline (speedup 1.0000x reference)
#include <cuda_runtime.h>
#include <math.h>
#include <stdint.h>

#define HIDD 128
#define KTOT 256
#define NMAX 100352
#define EMAX 602112

// ---------------- scratch (device globals; no allocation allowed) ----------
// g_cnt, g_bnsum, g_bnss rely on static zero-init; every kernel_launch call
// restores them to zero after use (scan3 / bnfin), so "zero at entry" holds
// across graph replays.
__device__ int   g_cnt[NMAX];
__device__ int   g_incl[NMAX];
__device__ int   g_bsum[256];
__device__ int   g_rowptr[NMAX + 1];
__device__ int   g_wpos[NMAX];
__device__ int   g_csr[EMAX];
__device__ float g_h0[(size_t)NMAX * HIDD];
__device__ float g_bnsum[HIDD];
__device__ float g_bnss[HIDD];
__device__ float g_scale[HIDD];
__device__ float g_shift[HIDD];
// B fragments: [layer][ (chunk16*16+ntile)*2+part ][64]  (uint32 bf16x2 pairs)
__device__ uint32_t g_Bfrag[2][16 * 16 * 2 * 64];
__device__ float g_bias2[HIDD];

// ---------------- helpers ---------------------------------------------------
__device__ __forceinline__ float bf16rd(float x) {
    float r;
    asm("{.reg .b16 t; cvt.rn.bf16.f32 t, %1; cvt.f32.bf16 %0, t;}"
        : "=f"(r) : "f"(x));
    return r;
}
__device__ __forceinline__ uint32_t pack2(float e0, float e1) {
    uint32_t r;
    asm("cvt.rn.bf16x2.f32 %0, %1, %2;" : "=r"(r) : "f"(e1), "f"(e0));
    return r;
}
__device__ __forceinline__ uint32_t smem_u32(const void* p) {
    uint32_t a;
    asm("{ .reg .u64 t; cvta.to.shared.u64 t, %1; cvt.u32.u64 %0, t; }"
        : "=r"(a) : "l"(p));
    return a;
}
__device__ __forceinline__ void ldm4(uint32_t* r, uint32_t addr) {
    asm volatile(
        "ldmatrix.sync.aligned.m8n8.x4.shared.b16 {%0,%1,%2,%3}, [%4];"
        : "=r"(r[0]), "=r"(r[1]), "=r"(r[2]), "=r"(r[3]) : "r"(addr));
}
__device__ __forceinline__ void mma16(float* c, const uint32_t* a, uint32_t b0,
                                      uint32_t b1) {
    asm volatile(
        "mma.sync.aligned.m16n8k16.row.col.f32.bf16.bf16.f32 "
        "{%0,%1,%2,%3},{%4,%5,%6,%7},{%8,%9},{%0,%1,%2,%3};"
        : "+f"(c[0]), "+f"(c[1]), "+f"(c[2]), "+f"(c[3])
        : "r"(a[0]), "r"(a[1]), "r"(a[2]), "r"(a[3]), "r"(b0), "r"(b1));
}

// ---------------- setup kernels ---------------------------------------------
__global__ void k_hist(const int* __restrict__ dst, int E) {
    int e = blockIdx.x * blockDim.x + threadIdx.x;
    if (e < E) atomicAdd(&g_cnt[dst[e]], 1);
}
__global__ void k_scan1(int n) {
    __shared__ int s[1024];
    int t = threadIdx.x;
    int i = blockIdx.x * 1024 + t;
    int v = (i < n) ? g_cnt[i] : 0;
    s[t] = v;
    __syncthreads();
    for (int off = 1; off < 1024; off <<= 1) {
        int x = (t >= off) ? s[t - off] : 0;
        __syncthreads();
        s[t] += x;
        __syncthreads();
    }
    if (i < n) g_incl[i] = s[t];
    if (t == 1023) g_bsum[blockIdx.x] = s[1023];
}
// scan2+scan3 fused; re-zeroes g_cnt for next call.
__global__ void k_scan3(int n, int E, int nb) {
    __shared__ int sb[128];
    int t = threadIdx.x;  // 256 threads
    if (t < 128) sb[t] = (t < nb) ? g_bsum[t] : 0;
    __syncthreads();
    for (int off = 1; off < 128; off <<= 1) {
        int x = 0;
        if (t < 128 && t >= off) x = sb[t - off];
        __syncthreads();
        if (t < 128) sb[t] += x;
        __syncthreads();
    }
    int i = blockIdx.x * blockDim.x + t;
    if (i < n) {
        int blk = i >> 10;
        int boff = (blk == 0) ? 0 : sb[blk - 1];
        int excl = g_incl[i] - g_cnt[i] + boff;
        g_rowptr[i] = excl;
        g_wpos[i] = excl;
        g_cnt[i] = 0;
        if (i == 0) g_rowptr[n] = E;
    }
}
__global__ void k_fill(const int* __restrict__ src, const int* __restrict__ dst, int E) {
    int e = blockIdx.x * blockDim.x + threadIdx.x;
    if (e < E) {
        int d = dst[e];
        int p = atomicAdd(&g_wpos[d], 1);
        g_csr[p] = src[e];
    }
}

// weight -> bf16 hi/lo b-fragments for m16n8k16 row.col
__global__ void k_prepw(const float* __restrict__ Wl, const float* __restrict__ Wr,
                        int layer, int useScale) {
    int idx = blockIdx.x * 256 + threadIdx.x;  // 16384 total
    int reg = idx & 1;
    int lane = (idx >> 1) & 31;
    int ntile = (idx >> 6) & 15;
    int chunk = idx >> 10;
    int tig = lane & 3, gcol = lane >> 2;
    int nn = ntile * 8 + gcol;
    int k0 = chunk * 16 + reg * 8 + tig * 2;
    int k1 = k0 + 1;
    float w0 = (k0 < HIDD) ? Wl[k0 * HIDD + nn] : Wr[(k0 - HIDD) * HIDD + nn];
    float w1 = (k1 < HIDD) ? Wl[k1 * HIDD + nn] : Wr[(k1 - HIDD) * HIDD + nn];
    if (useScale && k0 >= HIDD) {
        w0 *= g_scale[k0 - HIDD];
        w1 *= g_scale[k1 - HIDD];
    }
    float h0 = bf16rd(w0), h1 = bf16rd(w1);
    int base = ((chunk * 16 + ntile) * 2) * 64 + lane * 2 + reg;
    g_Bfrag[layer][base] = pack2(w0, w1);
    g_Bfrag[layer][base + 64] = pack2(w0 - h0, w1 - h1);
}

// BN finalize + bias2 fused. Re-zeroes g_bnsum/g_bnss.
__global__ void k_bnfin(const float* __restrict__ gamma, const float* __restrict__ beta,
                        const float* __restrict__ b2l, const float* __restrict__ W2r,
                        int n) {
    __shared__ float sh[HIDD];
    int c = threadIdx.x;  // 128 threads
    float mu = g_bnsum[c] / (float)n;
    float var = g_bnss[c] / (float)n - mu * mu;
    float sc = gamma[c] * rsqrtf(var + 1e-5f);
    float shf = beta[c] - mu * sc;
    g_scale[c] = sc;
    g_shift[c] = shf;
    sh[c] = shf;
    g_bnsum[c] = 0.f;
    g_bnss[c] = 0.f;
    __syncthreads();
    float s = b2l[c];
    for (int j = 0; j < HIDD; j++) s += sh[j] * W2r[j * HIDD + c];
    g_bias2[c] = s;
}

// ---------------- fused gather + GEMM (bf16 m16n8k16, 3-term) ---------------
// Block: 128 rows x 128 cols x K=256, 256 threads = 8 warps (4 mrow x 2 ncol).
// Phase 1: each warp gathers+averages neighbors for 16 of the block's rows
//          into smem meanS (layer2: applies BN scale/shift, deg>0 rule).
// Phase 2: GEMM; A mean-half staged from meanS (LDS), feat-half from gmem.
// LAYER 1 epilogue also accumulates BN column sums.
#define MEAN_STRIDE 132
#define DYN_SMEM (128 * MEAN_STRIDE * 4 + 2 * 2 * 1536 * 4)  // 92160

template <int LAYER>
__global__ __launch_bounds__(256, 2) void k_mma(
    const float* __restrict__ feat, const float* __restrict__ bias,
    const float* __restrict__ fcW, const float* __restrict__ fcb,
    float* __restrict__ outbuf, float* __restrict__ predout, int n) {
    extern __shared__ char dyn[];
    float* meanS = (float*)dyn;                             // 128*132 f32
    uint32_t* sAd = (uint32_t*)(dyn + 128 * MEAN_STRIDE * 4);  // [buf][part][1536]

    __shared__ float s_bias[128];
    __shared__ float s_fcw[64];
    __shared__ float s_ssq[128][2];
    __shared__ float bnS[128];
    __shared__ float bnQ[128];
    __shared__ float s_sc[128];
    __shared__ float s_sh[128];

    const int t = threadIdx.x;
    const int wid = t >> 5, lane = t & 31;
    const int wrow = wid >> 1, wcol = wid & 1;
    const int mtile = blockIdx.x * 128;

    if (t < 128) {
        s_bias[t] = bias[t];
        if (LAYER == 1) { bnS[t] = 0.f; bnQ[t] = 0.f; }
        if (LAYER == 2) { s_sc[t] = g_scale[t]; s_sh[t] = g_shift[t]; }
    }
    if (LAYER == 2 && t < 64) s_fcw[t] = fcW[t];
    if (LAYER == 2) __syncthreads();  // s_sc/s_sh ready before gather

    // ---- phase 1: gather mean rows into meanS ----
    {
        const float4* f4 = (const float4*)feat;
        for (int rr = 0; rr < 16; rr++) {
            int row = wid * 16 + rr;
            int m = mtile + row;
            float4 a = make_float4(0.f, 0.f, 0.f, 0.f);
            int deg = 0;
            if (m < n) {
                int r0 = g_rowptr[m], r1 = g_rowptr[m + 1];
                deg = r1 - r0;
                int j = r0;
                for (; j + 3 < r1; j += 4) {
                    int s0 = g_csr[j], s1 = g_csr[j + 1];
                    int s2 = g_csr[j + 2], s3 = g_csr[j + 3];
                    float4 v0 = f4[(size_t)s0 * 32 + lane];
                    float4 v1 = f4[(size_t)s1 * 32 + lane];
                    float4 v2 = f4[(size_t)s2 * 32 + lane];
                    float4 v3 = f4[(size_t)s3 * 32 + lane];
                    a.x += v0.x + v1.x + v2.x + v3.x;
                    a.y += v0.y + v1.y + v2.y + v3.y;
                    a.z += v0.z + v1.z + v2.z + v3.z;
                    a.w += v0.w + v1.w + v2.w + v3.w;
                }
                for (; j < r1; j++) {
                    int s0 = g_csr[j];
                    float4 v0 = f4[(size_t)s0 * 32 + lane];
                    a.x += v0.x; a.y += v0.y; a.z += v0.z; a.w += v0.w;
                }
            }
            float inv = (deg > 0) ? 1.f / (float)deg : 0.f;
            float4 mm = make_float4(a.x * inv, a.y * inv, a.z * inv, a.w * inv);
            if (LAYER == 2) {
                if (deg > 0) {
                    int c4 = lane * 4;
                    mm.x = mm.x * s_sc[c4] + s_sh[c4];
                    mm.y = mm.y * s_sc[c4 + 1] + s_sh[c4 + 1];
                    mm.z = mm.z * s_sc[c4 + 2] + s_sh[c4 + 2];
                    mm.w = mm.w * s_sc[c4 + 3] + s_sh[c4 + 3];
                } else {
                    mm = make_float4(0.f, 0.f, 0.f, 0.f);
                }
            }
            *(float4*)&meanS[row * MEAN_STRIDE + lane * 4] = mm;
        }
    }
    __syncthreads();

    // ---- phase 2: GEMM ----
    float acc[2][8][4];
#pragma unroll
    for (int ms = 0; ms < 2; ms++)
#pragma unroll
        for (int nt = 0; nt < 8; nt++)
#pragma unroll
            for (int j = 0; j < 4; j++) acc[ms][nt][j] = 0.f;

    const uint32_t* __restrict__ Bf = g_Bfrag[LAYER - 1];

    const int srow = t >> 1;       // staged row (0..127)
    const int kh = t & 1;          // k half -> 8 floats
    const uint32_t sAb = smem_u32(sAd);
    const int lrow = lane & 15;
    const int kpair = (lane >> 4) * 4;

    float4 pv0 = make_float4(0.f, 0.f, 0.f, 0.f), pv1 = pv0;

    for (int chunk = 0; chunk < 16; chunk++) {
        const int buf = chunk & 1;
        // ---- stage A chunk ----
        {
            float4 av0, av1;
            if (chunk < 8) {
                int kc = chunk * 16 + kh * 8;
                av0 = *(const float4*)&meanS[srow * MEAN_STRIDE + kc];
                av1 = *(const float4*)&meanS[srow * MEAN_STRIDE + kc + 4];
            } else {
                av0 = pv0;
                av1 = pv1;
            }
            float f[8] = {av0.x, av0.y, av0.z, av0.w, av1.x, av1.y, av1.z, av1.w};
            uint32_t hp[4], lp[4];
#pragma unroll
            for (int p = 0; p < 4; p++) {
                float e0 = f[2 * p], e1 = f[2 * p + 1];
                float h0 = bf16rd(e0), h1 = bf16rd(e1);
                hp[p] = pack2(e0, e1);
                lp[p] = pack2(e0 - h0, e1 - h1);
            }
            uint32_t* d0 = sAd + (buf * 2 + 0) * 1536 + srow * 12 + kh * 4;
            uint32_t* d1 = sAd + (buf * 2 + 1) * 1536 + srow * 12 + kh * 4;
            *(uint4*)d0 = make_uint4(hp[0], hp[1], hp[2], hp[3]);
            *(uint4*)d1 = make_uint4(lp[0], lp[1], lp[2], lp[3]);
        }
        __syncthreads();
        // ---- prefetch next feat chunk from gmem ----
        {
            int c1 = chunk + 1;
            if (c1 >= 8 && c1 < 16) {
                int kc = (c1 & 7) * 16 + kh * 8;
                int m = mtile + srow;
                if (m < n) {
                    const float* p = feat + (size_t)m * HIDD + kc;
                    pv0 = *(const float4*)p;
                    pv1 = *(const float4*)(p + 4);
                } else {
                    pv0 = make_float4(0.f, 0.f, 0.f, 0.f);
                    pv1 = pv0;
                }
            }
        }
        // ---- A fragments via ldmatrix ----
        uint32_t Ah[2][4], Al[2][4];
#pragma unroll
        for (int ms = 0; ms < 2; ms++) {
            int r = wrow * 32 + ms * 16 + lrow;
            uint32_t off = (uint32_t)(r * 12 + kpair) * 4u;
            ldm4(Ah[ms], sAb + buf * 12288u + off);
            ldm4(Al[ms], sAb + buf * 12288u + 6144u + off);
        }
        // ---- B hi fragments: hh + lh products ----
        uint32_t Bh[8][2];
#pragma unroll
        for (int nt = 0; nt < 8; nt++) {
            const uint32_t* bp =
                Bf + ((size_t)(chunk * 16 + wcol * 8 + nt) * 2) * 64 + lane * 2;
            Bh[nt][0] = bp[0];
            Bh[nt][1] = bp[1];
        }
#pragma unroll
        for (int ms = 0; ms < 2; ms++)
#pragma unroll
            for (int nt = 0; nt < 8; nt++) {
                mma16(acc[ms][nt], Ah[ms], Bh[nt][0], Bh[nt][1]);
                mma16(acc[ms][nt], Al[ms], Bh[nt][0], Bh[nt][1]);
            }
        // ---- B lo fragments: hl product ----
#pragma unroll
        for (int nt = 0; nt < 8; nt++) {
            const uint32_t* bp =
                Bf + ((size_t)(chunk * 16 + wcol * 8 + nt) * 2 + 1) * 64 + lane * 2;
            Bh[nt][0] = bp[0];
            Bh[nt][1] = bp[1];
        }
#pragma unroll
        for (int ms = 0; ms < 2; ms++)
#pragma unroll
            for (int nt = 0; nt < 8; nt++)
                mma16(acc[ms][nt], Ah[ms], Bh[nt][0], Bh[nt][1]);
    }

    // ---- epilogue ----
    const int g = lane >> 2, tig = lane & 3;
#pragma unroll
    for (int ms = 0; ms < 2; ms++) {
        float ss0 = 0.f, ss8 = 0.f;
#pragma unroll
        for (int nt = 0; nt < 8; nt++) {
            int col = wcol * 64 + nt * 8 + tig * 2;
            acc[ms][nt][0] += s_bias[col];
            acc[ms][nt][1] += s_bias[col + 1];
            acc[ms][nt][2] += s_bias[col];
            acc[ms][nt][3] += s_bias[col + 1];
            ss0 += acc[ms][nt][0] * acc[ms][nt][0] + acc[ms][nt][1] * acc[ms][nt][1];
            ss8 += acc[ms][nt][2] * acc[ms][nt][2] + acc[ms][nt][3] * acc[ms][nt][3];
        }
        ss0 += __shfl_xor_sync(0xffffffffu, ss0, 1);
        ss0 += __shfl_xor_sync(0xffffffffu, ss0, 2);
        ss8 += __shfl_xor_sync(0xffffffffu, ss8, 1);
        ss8 += __shfl_xor_sync(0xffffffffu, ss8, 2);
        if (tig == 0) {
            s_ssq[wrow * 32 + ms * 16 + g][wcol] = ss0;
            s_ssq[wrow * 32 + ms * 16 + g + 8][wcol] = ss8;
        }
    }
    __syncthreads();
#pragma unroll
    for (int ms = 0; ms < 2; ms++) {
        int lr = wrow * 32 + ms * 16 + g;
        int m0 = mtile + lr, m8 = m0 + 8;
        float inv0 = 1.0f / fmaxf(sqrtf(s_ssq[lr][0] + s_ssq[lr][1]), 1e-12f);
        float inv8 = 1.0f / fmaxf(sqrtf(s_ssq[lr + 8][0] + s_ssq[lr + 8][1]), 1e-12f);
        float pp0 = 0.f, pp8 = 0.f;
#pragma unroll
        for (int nt = 0; nt < 8; nt++) {
            int col = wcol * 64 + nt * 8 + tig * 2;
            float e0 = acc[ms][nt][0] * inv0;
            float e1 = acc[ms][nt][1] * inv0;
            float e2 = acc[ms][nt][2] * inv8;
            float e3 = acc[ms][nt][3] * inv8;
            if (LAYER == 1) {
                e0 = fmaxf(e0, 0.f); e1 = fmaxf(e1, 0.f);
                e2 = fmaxf(e2, 0.f); e3 = fmaxf(e3, 0.f);
            }
            if (m0 < n) *(float2*)(outbuf + (size_t)m0 * HIDD + col) = make_float2(e0, e1);
            if (m8 < n) *(float2*)(outbuf + (size_t)m8 * HIDD + col) = make_float2(e2, e3);
            if (LAYER == 1) {
                float a0 = (m0 < n) ? e0 : 0.f;
                float a1 = (m0 < n) ? e1 : 0.f;
                float a2 = (m8 < n) ? e2 : 0.f;
                float a3 = (m8 < n) ? e3 : 0.f;
                float sc0 = a0 + a2, sc1 = a1 + a3;
                float qc0 = a0 * a0 + a2 * a2, qc1 = a1 * a1 + a3 * a3;
#pragma unroll
                for (int o = 4; o < 32; o <<= 1) {
                    sc0 += __shfl_xor_sync(0xffffffffu, sc0, o);
                    sc1 += __shfl_xor_sync(0xffffffffu, sc1, o);
                    qc0 += __shfl_xor_sync(0xffffffffu, qc0, o);
                    qc1 += __shfl_xor_sync(0xffffffffu, qc1, o);
                }
                if (g == 0) {
                    atomicAdd(&bnS[col], sc0);
                    atomicAdd(&bnS[col + 1], sc1);
                    atomicAdd(&bnQ[col], qc0);
                    atomicAdd(&bnQ[col + 1], qc1);
                }
            }
            if (LAYER == 2 && wcol == 0) {
                pp0 += e0 * s_fcw[col] + e1 * s_fcw[col + 1];
                pp8 += e2 * s_fcw[col] + e3 * s_fcw[col + 1];
            }
        }
        if (LAYER == 2 && wcol == 0) {
            pp0 += __shfl_xor_sync(0xffffffffu, pp0, 1);
            pp0 += __shfl_xor_sync(0xffffffffu, pp0, 2);
            pp8 += __shfl_xor_sync(0xffffffffu, pp8, 1);
            pp8 += __shfl_xor_sync(0xffffffffu, pp8, 2);
            if (tig == 0) {
                float fb0 = fcb[0];
                if (m0 < n) predout[m0] = pp0 + fb0;
                if (m8 < n) predout[m8] = pp8 + fb0;
            }
        }
    }
    if (LAYER == 1) {
        __syncthreads();
        if (t < 128) {
            atomicAdd(&g_bnsum[t], bnS[t]);
            atomicAdd(&g_bnss[t], bnQ[t]);
        }
    }
}

// ---------------- launch ----------------------------------------------------
extern "C" void kernel_launch(void* const* d_in, const int* in_sizes, int n_in,
                              void* d_out, int out_size) {
    const float* x = (const float*)d_in[0];
    const int* ei = (const int*)d_in[1];
    const float* W1l = (const float*)d_in[2];
    const float* b1l = (const float*)d_in[3];
    const float* W1r = (const float*)d_in[4];
    const float* gamma = (const float*)d_in[5];
    const float* beta = (const float*)d_in[6];
    const float* W2l = (const float*)d_in[7];
    const float* b2l = (const float*)d_in[8];
    const float* W2r = (const float*)d_in[9];
    const float* fcW = (const float*)d_in[10];
    const float* fcb = (const float*)d_in[11];

    const int n = in_sizes[0] / HIDD;
    const int E = in_sizes[1] / 2;
    const int* src = ei;
    const int* dst = ei + E;

    float* preds = (float*)d_out;
    float* embed = (float*)d_out + n;

    float* gh0;    cudaGetSymbolAddress((void**)&gh0, g_h0);
    float* gbias2; cudaGetSymbolAddress((void**)&gbias2, g_bias2);

    // idempotent; not a captured stream op
    cudaFuncSetAttribute(k_mma<1>, cudaFuncAttributeMaxDynamicSharedMemorySize,
                         DYN_SMEM);
    cudaFuncSetAttribute(k_mma<2>, cudaFuncAttributeMaxDynamicSharedMemorySize,
                         DYN_SMEM);

    const int nb = (n + 1023) / 1024;
    const int gemmg = (n + 127) / 128;

    k_hist<<<(E + 255) / 256, 256>>>(dst, E);
    k_scan1<<<nb, 1024>>>(n);
    k_scan3<<<(n + 255) / 256, 256>>>(n, E, nb);
    k_fill<<<(E + 255) / 256, 256>>>(src, dst, E);
    k_prepw<<<64, 256>>>(W1l, W1r, 0, 0);

    // layer 1 (gather fused into GEMM)
    k_mma<1><<<gemmg, 256, DYN_SMEM>>>(x, b1l, nullptr, nullptr, gh0, nullptr, n);
    k_bnfin<<<1, 128>>>(gamma, beta, b2l, W2r, n);
    k_prepw<<<64, 256>>>(W2l, W2r, 1, 1);

    // layer 2
    k_mma<2><<<gemmg, 256, DYN_SMEM>>>(gh0, gbias2, fcW, fcb, embed, preds, n);
}

// round 11
// speedup vs baseline: 1.1623x; 1.1623x over previous
#include <cuda_runtime.h>
#include <math.h>
#include <stdint.h>

#define HIDD 128
#define KTOT 256
#define NMAX 100352
#define EMAX 602112

// ---------------- scratch (device globals; no allocation allowed) ----------
// g_cnt, g_bnsum, g_bnss rely on static zero-init; every kernel_launch call
// restores them to zero after use (scan3 / bnfin), so "zero at entry" holds
// across graph replays.
__device__ int   g_cnt[NMAX];
__device__ int   g_incl[NMAX];
__device__ int   g_bsum[256];
__device__ int   g_rowptr[NMAX + 1];
__device__ int   g_wpos[NMAX];
__device__ int   g_csr[EMAX];
__device__ float g_mean[(size_t)NMAX * HIDD];
__device__ float g_h0[(size_t)NMAX * HIDD];
__device__ float g_bnsum[HIDD];
__device__ float g_bnss[HIDD];
__device__ float g_scale[HIDD];
__device__ float g_shift[HIDD];
// B fragments (fp16x2): [layer][ (chunk16*16+ntile)*2+part ][64]
__device__ uint32_t g_Bfrag[2][16 * 16 * 2 * 64];
__device__ float g_bias2[HIDD];

// ---------------- helpers ---------------------------------------------------
__device__ __forceinline__ float f16rd(float x) {
    float r;
    asm("{.reg .b16 t; cvt.rn.f16.f32 t, %1; cvt.f32.f16 %0, t;}"
        : "=f"(r) : "f"(x));
    return r;
}
// pack: e0 -> low 16 bits, e1 -> high 16 bits (PTX: first src = upper half)
__device__ __forceinline__ uint32_t pack2h(float e0, float e1) {
    uint32_t r;
    asm("cvt.rn.f16x2.f32 %0, %1, %2;" : "=r"(r) : "f"(e1), "f"(e0));
    return r;
}
__device__ __forceinline__ uint32_t smem_u32(const void* p) {
    uint32_t a;
    asm("{ .reg .u64 t; cvta.to.shared.u64 t, %1; cvt.u32.u64 %0, t; }"
        : "=r"(a) : "l"(p));
    return a;
}
__device__ __forceinline__ void ldm4(uint32_t* r, uint32_t addr) {
    asm volatile(
        "ldmatrix.sync.aligned.m8n8.x4.shared.b16 {%0,%1,%2,%3}, [%4];"
        : "=r"(r[0]), "=r"(r[1]), "=r"(r[2]), "=r"(r[3]) : "r"(addr));
}
__device__ __forceinline__ void mma16(float* c, const uint32_t* a, uint32_t b0,
                                      uint32_t b1) {
    asm volatile(
        "mma.sync.aligned.m16n8k16.row.col.f32.f16.f16.f32 "
        "{%0,%1,%2,%3},{%4,%5,%6,%7},{%8,%9},{%0,%1,%2,%3};"
        : "+f"(c[0]), "+f"(c[1]), "+f"(c[2]), "+f"(c[3])
        : "r"(a[0]), "r"(a[1]), "r"(a[2]), "r"(a[3]), "r"(b0), "r"(b1));
}

// ---------------- setup kernels ---------------------------------------------
__global__ void k_hist(const int* __restrict__ dst, int E) {
    int e = blockIdx.x * blockDim.x + threadIdx.x;
    if (e < E) atomicAdd(&g_cnt[dst[e]], 1);
}
__global__ void k_scan1(int n) {
    __shared__ int s[1024];
    int t = threadIdx.x;
    int i = blockIdx.x * 1024 + t;
    int v = (i < n) ? g_cnt[i] : 0;
    s[t] = v;
    __syncthreads();
    for (int off = 1; off < 1024; off <<= 1) {
        int x = (t >= off) ? s[t - off] : 0;
        __syncthreads();
        s[t] += x;
        __syncthreads();
    }
    if (i < n) g_incl[i] = s[t];
    if (t == 1023) g_bsum[blockIdx.x] = s[1023];
}
// scan2+scan3 fused; re-zeroes g_cnt for next call.
__global__ void k_scan3(int n, int E, int nb) {
    __shared__ int sb[128];
    int t = threadIdx.x;  // 256 threads
    if (t < 128) sb[t] = (t < nb) ? g_bsum[t] : 0;
    __syncthreads();
    for (int off = 1; off < 128; off <<= 1) {
        int x = 0;
        if (t < 128 && t >= off) x = sb[t - off];
        __syncthreads();
        if (t < 128) sb[t] += x;
        __syncthreads();
    }
    int i = blockIdx.x * blockDim.x + t;
    if (i < n) {
        int blk = i >> 10;
        int boff = (blk == 0) ? 0 : sb[blk - 1];
        int excl = g_incl[i] - g_cnt[i] + boff;
        g_rowptr[i] = excl;
        g_wpos[i] = excl;
        g_cnt[i] = 0;
        if (i == 0) g_rowptr[n] = E;
    }
}
__global__ void k_fill(const int* __restrict__ src, const int* __restrict__ dst, int E) {
    int e = blockIdx.x * blockDim.x + threadIdx.x;
    if (e < E) {
        int d = dst[e];
        int p = atomicAdd(&g_wpos[d], 1);
        g_csr[p] = src[e];
    }
}

// weight -> fp16 hi/lo b-fragments for m16n8k16 row.col
__global__ void k_prepw(const float* __restrict__ Wl, const float* __restrict__ Wr,
                        int layer, int useScale) {
    int idx = blockIdx.x * 256 + threadIdx.x;  // 16384 total
    int reg = idx & 1;
    int lane = (idx >> 1) & 31;
    int ntile = (idx >> 6) & 15;
    int chunk = idx >> 10;
    int tig = lane & 3, gcol = lane >> 2;
    int nn = ntile * 8 + gcol;
    int k0 = chunk * 16 + reg * 8 + tig * 2;
    int k1 = k0 + 1;
    float w0 = (k0 < HIDD) ? Wl[k0 * HIDD + nn] : Wr[(k0 - HIDD) * HIDD + nn];
    float w1 = (k1 < HIDD) ? Wl[k1 * HIDD + nn] : Wr[(k1 - HIDD) * HIDD + nn];
    if (useScale && k0 >= HIDD) {
        w0 *= g_scale[k0 - HIDD];
        w1 *= g_scale[k1 - HIDD];
    }
    float h0 = f16rd(w0), h1 = f16rd(w1);
    int base = ((chunk * 16 + ntile) * 2) * 64 + lane * 2 + reg;
    g_Bfrag[layer][base] = pack2h(w0, w1);
    g_Bfrag[layer][base + 64] = pack2h(w0 - h0, w1 - h1);
}

// BN finalize + bias2 fused. Re-zeroes g_bnsum/g_bnss.
__global__ void k_bnfin(const float* __restrict__ gamma, const float* __restrict__ beta,
                        const float* __restrict__ b2l, const float* __restrict__ W2r,
                        int n) {
    __shared__ float sh[HIDD];
    int c = threadIdx.x;  // 128 threads
    float mu = g_bnsum[c] / (float)n;
    float var = g_bnss[c] / (float)n - mu * mu;
    float sc = gamma[c] * rsqrtf(var + 1e-5f);
    float shf = beta[c] - mu * sc;
    g_scale[c] = sc;
    g_shift[c] = shf;
    sh[c] = shf;
    g_bnsum[c] = 0.f;
    g_bnss[c] = 0.f;
    __syncthreads();
    float s = b2l[c];
    for (int j = 0; j < HIDD; j++) s += sh[j] * W2r[j * HIDD + c];
    g_bias2[c] = s;
}

// ---------------- aggregation: one warp per node, 4-way unroll --------------
__global__ void k_agg(const float* __restrict__ feat, float* __restrict__ outm,
                      int n, int layer2) {
    int w = (blockIdx.x * blockDim.x + threadIdx.x) >> 5;
    int lane = threadIdx.x & 31;
    if (w >= n) return;
    int r0 = g_rowptr[w], r1 = g_rowptr[w + 1];
    const float4* f4 = (const float4*)feat;
    float4 a = make_float4(0.f, 0.f, 0.f, 0.f);
    int j = r0;
    for (; j + 3 < r1; j += 4) {
        int s0 = g_csr[j];
        int s1 = g_csr[j + 1];
        int s2 = g_csr[j + 2];
        int s3 = g_csr[j + 3];
        float4 v0 = f4[(size_t)s0 * 32 + lane];
        float4 v1 = f4[(size_t)s1 * 32 + lane];
        float4 v2 = f4[(size_t)s2 * 32 + lane];
        float4 v3 = f4[(size_t)s3 * 32 + lane];
        a.x += v0.x + v1.x + v2.x + v3.x;
        a.y += v0.y + v1.y + v2.y + v3.y;
        a.z += v0.z + v1.z + v2.z + v3.z;
        a.w += v0.w + v1.w + v2.w + v3.w;
    }
    for (; j < r1; j++) {
        int s0 = g_csr[j];
        float4 v0 = f4[(size_t)s0 * 32 + lane];
        a.x += v0.x; a.y += v0.y; a.z += v0.z; a.w += v0.w;
    }
    int deg = r1 - r0;
    float inv = (deg > 0) ? 1.f / (float)deg : 0.f;
    float4 m = make_float4(a.x * inv, a.y * inv, a.z * inv, a.w * inv);
    if (layer2) {
        if (deg > 0) {
            float4 sc = *(const float4*)(g_scale + lane * 4);
            float4 sh = *(const float4*)(g_shift + lane * 4);
            m.x = m.x * sc.x + sh.x; m.y = m.y * sc.y + sh.y;
            m.z = m.z * sc.z + sh.z; m.w = m.w * sc.w + sh.w;
        } else {
            m = make_float4(0.f, 0.f, 0.f, 0.f);
        }
    }
    ((float4*)outm)[(size_t)w * 32 + lane] = m;
}

// ---------------- GEMM via fp16 m16n8k16 mma (A single, B hi+lo) ------------
// Block: 128 rows x 128 cols x K=256, 256 threads = 8 warps (4 mrow x 2 ncol).
// LAYER 1 epilogue also accumulates BN column sums.
template <int LAYER>
__global__ __launch_bounds__(256, 2) void k_mma(
    const float* __restrict__ meanbuf, const float* __restrict__ featbuf,
    const float* __restrict__ bias, const float* __restrict__ fcW,
    const float* __restrict__ fcb, float* __restrict__ outbuf,
    float* __restrict__ predout, int n) {
    __shared__ __align__(16) uint32_t sA[2][128 * 12];  // [buf][row*12+pair]
    __shared__ float s_bias[128];
    __shared__ float s_fcw[64];
    __shared__ float s_ssq[128][2];
    __shared__ float bnS[128];
    __shared__ float bnQ[128];

    const int t = threadIdx.x;
    const int wid = t >> 5, lane = t & 31;
    const int wrow = wid >> 1, wcol = wid & 1;
    const int mtile = blockIdx.x * 128;

    if (t < 128) {
        s_bias[t] = bias[t];
        if (LAYER == 1) { bnS[t] = 0.f; bnQ[t] = 0.f; }
    }
    if (LAYER == 2 && t < 64) s_fcw[t] = fcW[t];

    float acc[2][8][4];
#pragma unroll
    for (int ms = 0; ms < 2; ms++)
#pragma unroll
        for (int nt = 0; nt < 8; nt++)
#pragma unroll
            for (int j = 0; j < 4; j++) acc[ms][nt][j] = 0.f;

    const uint32_t* __restrict__ Bf = g_Bfrag[LAYER - 1];

    const int srow = t >> 1;       // staged row (0..127)
    const int kh = t & 1;          // k half -> 8 floats
    const uint32_t sAb = smem_u32(&sA[0][0]);
    const int lrow = lane & 15;
    const int kpair = (lane >> 4) * 4;

    // prefetch chunk 0
    float4 av0 = make_float4(0.f, 0.f, 0.f, 0.f), av1 = av0;
    {
        int m = mtile + srow;
        if (m < n) {
            const float* p = meanbuf + (size_t)m * HIDD + kh * 8;
            av0 = *(const float4*)p;
            av1 = *(const float4*)(p + 4);
        }
    }

    for (int chunk = 0; chunk < 16; chunk++) {
        const int buf = chunk & 1;
        // ---- stage A chunk (single fp16, no residual) ----
        {
            uint32_t hp0 = pack2h(av0.x, av0.y);
            uint32_t hp1 = pack2h(av0.z, av0.w);
            uint32_t hp2 = pack2h(av1.x, av1.y);
            uint32_t hp3 = pack2h(av1.z, av1.w);
            *(uint4*)&sA[buf][srow * 12 + kh * 4] = make_uint4(hp0, hp1, hp2, hp3);
        }
        __syncthreads();
        // ---- prefetch next chunk ----
        if (chunk < 15) {
            int c1 = chunk + 1;
            const float* src = (c1 < 8) ? meanbuf : featbuf;
            int kc = (c1 & 7) * 16 + kh * 8;
            int m = mtile + srow;
            if (m < n) {
                const float* p = src + (size_t)m * HIDD + kc;
                av0 = *(const float4*)p;
                av1 = *(const float4*)(p + 4);
            } else {
                av0 = make_float4(0.f, 0.f, 0.f, 0.f);
                av1 = av0;
            }
        }
        // ---- A fragments via ldmatrix ----
        uint32_t Ah[2][4];
#pragma unroll
        for (int ms = 0; ms < 2; ms++) {
            int r = wrow * 32 + ms * 16 + lrow;
            uint32_t off = (uint32_t)(r * 12 + kpair) * 4u;
            ldm4(Ah[ms], sAb + buf * 6144u + off);
        }
        // ---- B hi fragments ----
        uint32_t Bh[8][2];
#pragma unroll
        for (int nt = 0; nt < 8; nt++) {
            const uint32_t* bp =
                Bf + ((size_t)(chunk * 16 + wcol * 8 + nt) * 2) * 64 + lane * 2;
            Bh[nt][0] = bp[0];
            Bh[nt][1] = bp[1];
        }
#pragma unroll
        for (int ms = 0; ms < 2; ms++)
#pragma unroll
            for (int nt = 0; nt < 8; nt++)
                mma16(acc[ms][nt], Ah[ms], Bh[nt][0], Bh[nt][1]);
        // ---- B lo fragments ----
#pragma unroll
        for (int nt = 0; nt < 8; nt++) {
            const uint32_t* bp =
                Bf + ((size_t)(chunk * 16 + wcol * 8 + nt) * 2 + 1) * 64 + lane * 2;
            Bh[nt][0] = bp[0];
            Bh[nt][1] = bp[1];
        }
#pragma unroll
        for (int ms = 0; ms < 2; ms++)
#pragma unroll
            for (int nt = 0; nt < 8; nt++)
                mma16(acc[ms][nt], Ah[ms], Bh[nt][0], Bh[nt][1]);
    }

    // ---- epilogue ----
    const int g = lane >> 2, tig = lane & 3;
#pragma unroll
    for (int ms = 0; ms < 2; ms++) {
        float ss0 = 0.f, ss8 = 0.f;
#pragma unroll
        for (int nt = 0; nt < 8; nt++) {
            int col = wcol * 64 + nt * 8 + tig * 2;
            acc[ms][nt][0] += s_bias[col];
            acc[ms][nt][1] += s_bias[col + 1];
            acc[ms][nt][2] += s_bias[col];
            acc[ms][nt][3] += s_bias[col + 1];
            ss0 += acc[ms][nt][0] * acc[ms][nt][0] + acc[ms][nt][1] * acc[ms][nt][1];
            ss8 += acc[ms][nt][2] * acc[ms][nt][2] + acc[ms][nt][3] * acc[ms][nt][3];
        }
        ss0 += __shfl_xor_sync(0xffffffffu, ss0, 1);
        ss0 += __shfl_xor_sync(0xffffffffu, ss0, 2);
        ss8 += __shfl_xor_sync(0xffffffffu, ss8, 1);
        ss8 += __shfl_xor_sync(0xffffffffu, ss8, 2);
        if (tig == 0) {
            s_ssq[wrow * 32 + ms * 16 + g][wcol] = ss0;
            s_ssq[wrow * 32 + ms * 16 + g + 8][wcol] = ss8;
        }
    }
    __syncthreads();
#pragma unroll
    for (int ms = 0; ms < 2; ms++) {
        int lr = wrow * 32 + ms * 16 + g;
        int m0 = mtile + lr, m8 = m0 + 8;
        float inv0 = 1.0f / fmaxf(sqrtf(s_ssq[lr][0] + s_ssq[lr][1]), 1e-12f);
        float inv8 = 1.0f / fmaxf(sqrtf(s_ssq[lr + 8][0] + s_ssq[lr + 8][1]), 1e-12f);
        float pp0 = 0.f, pp8 = 0.f;
#pragma unroll
        for (int nt = 0; nt < 8; nt++) {
            int col = wcol * 64 + nt * 8 + tig * 2;
            float e0 = acc[ms][nt][0] * inv0;
            float e1 = acc[ms][nt][1] * inv0;
            float e2 = acc[ms][nt][2] * inv8;
            float e3 = acc[ms][nt][3] * inv8;
            if (LAYER == 1) {
                e0 = fmaxf(e0, 0.f); e1 = fmaxf(e1, 0.f);
                e2 = fmaxf(e2, 0.f); e3 = fmaxf(e3, 0.f);
            }
            if (m0 < n) *(float2*)(outbuf + (size_t)m0 * HIDD + col) = make_float2(e0, e1);
            if (m8 < n) *(float2*)(outbuf + (size_t)m8 * HIDD + col) = make_float2(e2, e3);
            if (LAYER == 1) {
                float a0 = (m0 < n) ? e0 : 0.f;
                float a1 = (m0 < n) ? e1 : 0.f;
                float a2 = (m8 < n) ? e2 : 0.f;
                float a3 = (m8 < n) ? e3 : 0.f;
                float sc0 = a0 + a2, sc1 = a1 + a3;
                float qc0 = a0 * a0 + a2 * a2, qc1 = a1 * a1 + a3 * a3;
#pragma unroll
                for (int o = 4; o < 32; o <<= 1) {
                    sc0 += __shfl_xor_sync(0xffffffffu, sc0, o);
                    sc1 += __shfl_xor_sync(0xffffffffu, sc1, o);
                    qc0 += __shfl_xor_sync(0xffffffffu, qc0, o);
                    qc1 += __shfl_xor_sync(0xffffffffu, qc1, o);
                }
                if (g == 0) {
                    atomicAdd(&bnS[col], sc0);
                    atomicAdd(&bnS[col + 1], sc1);
                    atomicAdd(&bnQ[col], qc0);
                    atomicAdd(&bnQ[col + 1], qc1);
                }
            }
            if (LAYER == 2 && wcol == 0) {
                pp0 += e0 * s_fcw[col] + e1 * s_fcw[col + 1];
                pp8 += e2 * s_fcw[col] + e3 * s_fcw[col + 1];
            }
        }
        if (LAYER == 2 && wcol == 0) {
            pp0 += __shfl_xor_sync(0xffffffffu, pp0, 1);
            pp0 += __shfl_xor_sync(0xffffffffu, pp0, 2);
            pp8 += __shfl_xor_sync(0xffffffffu, pp8, 1);
            pp8 += __shfl_xor_sync(0xffffffffu, pp8, 2);
            if (tig == 0) {
                float fb0 = fcb[0];
                if (m0 < n) predout[m0] = pp0 + fb0;
                if (m8 < n) predout[m8] = pp8 + fb0;
            }
        }
    }
    if (LAYER == 1) {
        __syncthreads();
        if (t < 128) {
            atomicAdd(&g_bnsum[t], bnS[t]);
            atomicAdd(&g_bnss[t], bnQ[t]);
        }
    }
}

// ---------------- launch ----------------------------------------------------
extern "C" void kernel_launch(void* const* d_in, const int* in_sizes, int n_in,
                              void* d_out, int out_size) {
    const float* x = (const float*)d_in[0];
    const int* ei = (const int*)d_in[1];
    const float* W1l = (const float*)d_in[2];
    const float* b1l = (const float*)d_in[3];
    const float* W1r = (const float*)d_in[4];
    const float* gamma = (const float*)d_in[5];
    const float* beta = (const float*)d_in[6];
    const float* W2l = (const float*)d_in[7];
    const float* b2l = (const float*)d_in[8];
    const float* W2r = (const float*)d_in[9];
    const float* fcW = (const float*)d_in[10];
    const float* fcb = (const float*)d_in[11];

    const int n = in_sizes[0] / HIDD;
    const int E = in_sizes[1] / 2;
    const int* src = ei;
    const int* dst = ei + E;

    float* preds = (float*)d_out;
    float* embed = (float*)d_out + n;

    float* gmean;  cudaGetSymbolAddress((void**)&gmean, g_mean);
    float* gh0;    cudaGetSymbolAddress((void**)&gh0, g_h0);
    float* gbias2; cudaGetSymbolAddress((void**)&gbias2, g_bias2);

    const int nb = (n + 1023) / 1024;
    const int gemmg = (n + 127) / 128;

    k_hist<<<(E + 255) / 256, 256>>>(dst, E);
    k_scan1<<<nb, 1024>>>(n);
    k_scan3<<<(n + 255) / 256, 256>>>(n, E, nb);
    k_fill<<<(E + 255) / 256, 256>>>(src, dst, E);
    k_prepw<<<64, 256>>>(W1l, W1r, 0, 0);

    // layer 1
    k_agg<<<(n + 7) / 8, 256>>>(x, gmean, n, 0);
    k_mma<1><<<gemmg, 256>>>(gmean, x, b1l, nullptr, nullptr, gh0, nullptr, n);
    k_bnfin<<<1, 128>>>(gamma, beta, b2l, W2r, n);
    k_prepw<<<64, 256>>>(W2l, W2r, 1, 1);

    // layer 2
    k_agg<<<(n + 7) / 8, 256>>>(gh0, gmean, n, 1);
    k_mma<2><<<gemmg, 256>>>(gmean, gh0, gbias2, fcW, fcb, embed, preds, n);
}

// round 14
// speedup vs baseline: 1.3904x; 1.1963x over previous
#include <cuda_runtime.h>
#include <math.h>
#include <stdint.h>

#define HIDD 128
#define NMAX 100352
#define EMAX 602112

// ---------------- scratch (device globals; no allocation allowed) ----------
// g_cnt, g_bnsum, g_bnss rely on static zero-init; every kernel_launch call
// restores them to zero after use (scan3 / bnfin), so "zero at entry" holds
// across graph replays.
__device__ int   g_cnt[NMAX];
__device__ int   g_incl[NMAX];
__device__ int   g_bsum[256];
__device__ int   g_rowptr[NMAX + 1];
__device__ int   g_wpos[NMAX];
__device__ int   g_csr[EMAX];
__device__ uint32_t g_xh[(size_t)NMAX * 64];     // x as fp16x2
__device__ uint32_t g_h0h[(size_t)NMAX * 64];    // h0 as fp16x2
__device__ uint32_t g_meanh[(size_t)NMAX * 64];  // mean as fp16x2
__device__ float g_bnsum[HIDD];
__device__ float g_bnss[HIDD];
__device__ float g_scale[HIDD];
__device__ float g_shift[HIDD];
// B fragments (fp16x2): [layer][ (chunk16*16+ntile)*2+part ][64]
__device__ uint32_t g_Bfrag[2][16 * 16 * 2 * 64];
__device__ float g_bias2[HIDD];

// ---------------- helpers ---------------------------------------------------
__device__ __forceinline__ float f16rd(float x) {
    float r;
    asm("{.reg .b16 t; cvt.rn.f16.f32 t, %1; cvt.f32.f16 %0, t;}"
        : "=f"(r) : "f"(x));
    return r;
}
// pack: e0 -> low 16 bits, e1 -> high 16 bits (PTX: first src = upper half)
__device__ __forceinline__ uint32_t pack2h(float e0, float e1) {
    uint32_t r;
    asm("cvt.rn.f16x2.f32 %0, %1, %2;" : "=r"(r) : "f"(e1), "f"(e0));
    return r;
}
__device__ __forceinline__ float2 h2f(uint32_t u) {
    float2 r;
    asm("{.reg .b16 lo,hi; mov.b32 {lo,hi}, %2; cvt.f32.f16 %0, lo; cvt.f32.f16 %1, hi;}"
        : "=f"(r.x), "=f"(r.y) : "r"(u));
    return r;
}
__device__ __forceinline__ uint32_t smem_u32(const void* p) {
    uint32_t a;
    asm("{ .reg .u64 t; cvta.to.shared.u64 t, %1; cvt.u32.u64 %0, t; }"
        : "=r"(a) : "l"(p));
    return a;
}
__device__ __forceinline__ void ldm4(uint32_t* r, uint32_t addr) {
    asm volatile(
        "ldmatrix.sync.aligned.m8n8.x4.shared.b16 {%0,%1,%2,%3}, [%4];"
        : "=r"(r[0]), "=r"(r[1]), "=r"(r[2]), "=r"(r[3]) : "r"(addr));
}
__device__ __forceinline__ void mma16(float* c, const uint32_t* a, uint32_t b0,
                                      uint32_t b1) {
    asm volatile(
        "mma.sync.aligned.m16n8k16.row.col.f32.f16.f16.f32 "
        "{%0,%1,%2,%3},{%4,%5,%6,%7},{%8,%9},{%0,%1,%2,%3};"
        : "+f"(c[0]), "+f"(c[1]), "+f"(c[2]), "+f"(c[3])
        : "r"(a[0]), "r"(a[1]), "r"(a[2]), "r"(a[3]), "r"(b0), "r"(b1));
}

// ---------------- setup kernels ---------------------------------------------
__global__ void k_hist(const int* __restrict__ dst, int E) {
    int e = blockIdx.x * blockDim.x + threadIdx.x;
    if (e < E) atomicAdd(&g_cnt[dst[e]], 1);
}
__global__ void k_scan1(int n) {
    __shared__ int s[1024];
    int t = threadIdx.x;
    int i = blockIdx.x * 1024 + t;
    int v = (i < n) ? g_cnt[i] : 0;
    s[t] = v;
    __syncthreads();
    for (int off = 1; off < 1024; off <<= 1) {
        int x = (t >= off) ? s[t - off] : 0;
        __syncthreads();
        s[t] += x;
        __syncthreads();
    }
    if (i < n) g_incl[i] = s[t];
    if (t == 1023) g_bsum[blockIdx.x] = s[1023];
}
// scan2+scan3 fused; re-zeroes g_cnt for next call.
__global__ void k_scan3(int n, int E, int nb) {
    __shared__ int sb[128];
    int t = threadIdx.x;  // 256 threads
    if (t < 128) sb[t] = (t < nb) ? g_bsum[t] : 0;
    __syncthreads();
    for (int off = 1; off < 128; off <<= 1) {
        int x = 0;
        if (t < 128 && t >= off) x = sb[t - off];
        __syncthreads();
        if (t < 128) sb[t] += x;
        __syncthreads();
    }
    int i = blockIdx.x * blockDim.x + t;
    if (i < n) {
        int blk = i >> 10;
        int boff = (blk == 0) ? 0 : sb[blk - 1];
        int excl = g_incl[i] - g_cnt[i] + boff;
        g_rowptr[i] = excl;
        g_wpos[i] = excl;
        g_cnt[i] = 0;
        if (i == 0) g_rowptr[n] = E;
    }
}
__global__ void k_fill(const int* __restrict__ src, const int* __restrict__ dst, int E) {
    int e = blockIdx.x * blockDim.x + threadIdx.x;
    if (e < E) {
        int d = dst[e];
        int p = atomicAdd(&g_wpos[d], 1);
        g_csr[p] = src[e];
    }
}
// x -> fp16x2
__global__ void k_cvtx(const float* __restrict__ x, int n) {
    int i = blockIdx.x * 256 + threadIdx.x;  // n*32 total
    if (i < n * 32) {
        float4 v = ((const float4*)x)[i];
        uint2 o;
        o.x = pack2h(v.x, v.y);
        o.y = pack2h(v.z, v.w);
        ((uint2*)g_xh)[i] = o;
    }
}

// weight -> fp16 hi/lo b-fragments for m16n8k16 row.col
__global__ void k_prepw(const float* __restrict__ Wl, const float* __restrict__ Wr,
                        int layer, int useScale) {
    int idx = blockIdx.x * 256 + threadIdx.x;  // 16384 total
    int reg = idx & 1;
    int lane = (idx >> 1) & 31;
    int ntile = (idx >> 6) & 15;
    int chunk = idx >> 10;
    int tig = lane & 3, gcol = lane >> 2;
    int nn = ntile * 8 + gcol;
    int k0 = chunk * 16 + reg * 8 + tig * 2;
    int k1 = k0 + 1;
    float w0 = (k0 < HIDD) ? Wl[k0 * HIDD + nn] : Wr[(k0 - HIDD) * HIDD + nn];
    float w1 = (k1 < HIDD) ? Wl[k1 * HIDD + nn] : Wr[(k1 - HIDD) * HIDD + nn];
    if (useScale && k0 >= HIDD) {
        w0 *= g_scale[k0 - HIDD];
        w1 *= g_scale[k1 - HIDD];
    }
    float h0 = f16rd(w0), h1 = f16rd(w1);
    int base = ((chunk * 16 + ntile) * 2) * 64 + lane * 2 + reg;
    g_Bfrag[layer][base] = pack2h(w0, w1);
    g_Bfrag[layer][base + 64] = pack2h(w0 - h0, w1 - h1);
}

// BN finalize + bias2 fused. Re-zeroes g_bnsum/g_bnss.
__global__ void k_bnfin(const float* __restrict__ gamma, const float* __restrict__ beta,
                        const float* __restrict__ b2l, const float* __restrict__ W2r,
                        int n) {
    __shared__ float sh[HIDD];
    int c = threadIdx.x;  // 128 threads
    float mu = g_bnsum[c] / (float)n;
    float var = g_bnss[c] / (float)n - mu * mu;
    float sc = gamma[c] * rsqrtf(var + 1e-5f);
    float shf = beta[c] - mu * sc;
    g_scale[c] = sc;
    g_shift[c] = shf;
    sh[c] = shf;
    g_bnsum[c] = 0.f;
    g_bnss[c] = 0.f;
    __syncthreads();
    float s = b2l[c];
    for (int j = 0; j < HIDD; j++) s += sh[j] * W2r[j * HIDD + c];
    g_bias2[c] = s;
}

// ---------------- aggregation: fp16x2 gather, fp32 accumulate ---------------
// One warp per node; each lane owns 4 features (one uint2 = 4 halves).
__global__ void k_agg(const uint32_t* __restrict__ feat, int n, int layer2) {
    int w = (blockIdx.x * blockDim.x + threadIdx.x) >> 5;
    int lane = threadIdx.x & 31;
    if (w >= n) return;
    int r0 = g_rowptr[w], r1 = g_rowptr[w + 1];
    const uint2* f2 = (const uint2*)feat;
    float a0 = 0.f, a1 = 0.f, a2 = 0.f, a3 = 0.f;
    int j = r0;
    for (; j + 3 < r1; j += 4) {
        int s0 = g_csr[j], s1 = g_csr[j + 1];
        int s2 = g_csr[j + 2], s3 = g_csr[j + 3];
        uint2 v0 = f2[(size_t)s0 * 32 + lane];
        uint2 v1 = f2[(size_t)s1 * 32 + lane];
        uint2 v2 = f2[(size_t)s2 * 32 + lane];
        uint2 v3 = f2[(size_t)s3 * 32 + lane];
        float2 p;
        p = h2f(v0.x); a0 += p.x; a1 += p.y;
        p = h2f(v0.y); a2 += p.x; a3 += p.y;
        p = h2f(v1.x); a0 += p.x; a1 += p.y;
        p = h2f(v1.y); a2 += p.x; a3 += p.y;
        p = h2f(v2.x); a0 += p.x; a1 += p.y;
        p = h2f(v2.y); a2 += p.x; a3 += p.y;
        p = h2f(v3.x); a0 += p.x; a1 += p.y;
        p = h2f(v3.y); a2 += p.x; a3 += p.y;
    }
    for (; j < r1; j++) {
        int s0 = g_csr[j];
        uint2 v0 = f2[(size_t)s0 * 32 + lane];
        float2 p;
        p = h2f(v0.x); a0 += p.x; a1 += p.y;
        p = h2f(v0.y); a2 += p.x; a3 += p.y;
    }
    int deg = r1 - r0;
    float inv = (deg > 0) ? 1.f / (float)deg : 0.f;
    float m0 = a0 * inv, m1 = a1 * inv, m2 = a2 * inv, m3 = a3 * inv;
    if (layer2) {
        if (deg > 0) {
            float4 sc = *(const float4*)(g_scale + lane * 4);
            float4 sh = *(const float4*)(g_shift + lane * 4);
            m0 = m0 * sc.x + sh.x;
            m1 = m1 * sc.y + sh.y;
            m2 = m2 * sc.z + sh.z;
            m3 = m3 * sc.w + sh.w;
        } else {
            m0 = m1 = m2 = m3 = 0.f;
        }
    }
    uint2 o;
    o.x = pack2h(m0, m1);
    o.y = pack2h(m2, m3);
    ((uint2*)g_meanh)[(size_t)w * 32 + lane] = o;
}

// ---------------- GEMM via fp16 m16n8k16 mma (A single, B hi+lo) ------------
// Block: 128 rows x 128 cols x K=256, 256 threads = 8 warps (4 mrow x 2 ncol).
// A operands are pre-quantized fp16x2 in gmem -> staging is a pure uint4 copy.
// LAYER 1: writes h0 as fp16x2 + BN column sums. LAYER 2: embed fp32 + preds.
template <int LAYER>
__global__ __launch_bounds__(256, 2) void k_mma(
    const uint32_t* __restrict__ meanbuf, const uint32_t* __restrict__ featbuf,
    const float* __restrict__ bias, const float* __restrict__ fcW,
    const float* __restrict__ fcb, uint32_t* __restrict__ h16out,
    float* __restrict__ embout, float* __restrict__ predout, int n) {
    __shared__ __align__(16) uint32_t sA[2][128 * 12];  // [buf][row*12+pair]
    __shared__ float s_bias[128];
    __shared__ float s_fcw[64];
    __shared__ float s_ssq[128][2];
    __shared__ float bnS[128];
    __shared__ float bnQ[128];

    const int t = threadIdx.x;
    const int wid = t >> 5, lane = t & 31;
    const int wrow = wid >> 1, wcol = wid & 1;
    const int mtile = blockIdx.x * 128;

    if (t < 128) {
        s_bias[t] = bias[t];
        if (LAYER == 1) { bnS[t] = 0.f; bnQ[t] = 0.f; }
    }
    if (LAYER == 2 && t < 64) s_fcw[t] = fcW[t];

    float acc[2][8][4];
#pragma unroll
    for (int ms = 0; ms < 2; ms++)
#pragma unroll
        for (int nt = 0; nt < 8; nt++)
#pragma unroll
            for (int j = 0; j < 4; j++) acc[ms][nt][j] = 0.f;

    const uint32_t* __restrict__ Bf = g_Bfrag[LAYER - 1];

    const int srow = t >> 1;       // staged row (0..127)
    const int kh = t & 1;          // k half -> 4 uint32 (8 halves)
    const uint32_t sAb = smem_u32(&sA[0][0]);
    const int lrow = lane & 15;
    const int kpair = (lane >> 4) * 4;
    const int m_st = mtile + srow;
    const bool mok = (m_st < n);

    // prefetch chunk 0
    uint4 av = make_uint4(0u, 0u, 0u, 0u);
    if (mok) av = *(const uint4*)(meanbuf + (size_t)m_st * 64 + kh * 4);

    for (int chunk = 0; chunk < 16; chunk++) {
        const int buf = chunk & 1;
        // ---- stage A chunk: pure copy ----
        *(uint4*)&sA[buf][srow * 12 + kh * 4] = av;
        __syncthreads();
        // ---- prefetch next chunk ----
        if (chunk < 15) {
            int c1 = chunk + 1;
            const uint32_t* src = (c1 < 8) ? meanbuf : featbuf;
            int kc = (c1 & 7) * 8 + kh * 4;
            av = mok ? *(const uint4*)(src + (size_t)m_st * 64 + kc)
                     : make_uint4(0u, 0u, 0u, 0u);
        }
        // ---- A fragments via ldmatrix ----
        uint32_t Ah[2][4];
#pragma unroll
        for (int ms = 0; ms < 2; ms++) {
            int r = wrow * 32 + ms * 16 + lrow;
            uint32_t off = (uint32_t)(r * 12 + kpair) * 4u;
            ldm4(Ah[ms], sAb + buf * 6144u + off);
        }
        // ---- B hi fragments ----
        uint32_t Bh[8][2];
#pragma unroll
        for (int nt = 0; nt < 8; nt++) {
            const uint32_t* bp =
                Bf + ((size_t)(chunk * 16 + wcol * 8 + nt) * 2) * 64 + lane * 2;
            Bh[nt][0] = bp[0];
            Bh[nt][1] = bp[1];
        }
#pragma unroll
        for (int ms = 0; ms < 2; ms++)
#pragma unroll
            for (int nt = 0; nt < 8; nt++)
                mma16(acc[ms][nt], Ah[ms], Bh[nt][0], Bh[nt][1]);
        // ---- B lo fragments ----
#pragma unroll
        for (int nt = 0; nt < 8; nt++) {
            const uint32_t* bp =
                Bf + ((size_t)(chunk * 16 + wcol * 8 + nt) * 2 + 1) * 64 + lane * 2;
            Bh[nt][0] = bp[0];
            Bh[nt][1] = bp[1];
        }
#pragma unroll
        for (int ms = 0; ms < 2; ms++)
#pragma unroll
            for (int nt = 0; nt < 8; nt++)
                mma16(acc[ms][nt], Ah[ms], Bh[nt][0], Bh[nt][1]);
    }

    // ---- epilogue ----
    const int g = lane >> 2, tig = lane & 3;
#pragma unroll
    for (int ms = 0; ms < 2; ms++) {
        float ss0 = 0.f, ss8 = 0.f;
#pragma unroll
        for (int nt = 0; nt < 8; nt++) {
            int col = wcol * 64 + nt * 8 + tig * 2;
            acc[ms][nt][0] += s_bias[col];
            acc[ms][nt][1] += s_bias[col + 1];
            acc[ms][nt][2] += s_bias[col];
            acc[ms][nt][3] += s_bias[col + 1];
            ss0 += acc[ms][nt][0] * acc[ms][nt][0] + acc[ms][nt][1] * acc[ms][nt][1];
            ss8 += acc[ms][nt][2] * acc[ms][nt][2] + acc[ms][nt][3] * acc[ms][nt][3];
        }
        ss0 += __shfl_xor_sync(0xffffffffu, ss0, 1);
        ss0 += __shfl_xor_sync(0xffffffffu, ss0, 2);
        ss8 += __shfl_xor_sync(0xffffffffu, ss8, 1);
        ss8 += __shfl_xor_sync(0xffffffffu, ss8, 2);
        if (tig == 0) {
            s_ssq[wrow * 32 + ms * 16 + g][wcol] = ss0;
            s_ssq[wrow * 32 + ms * 16 + g + 8][wcol] = ss8;
        }
    }
    __syncthreads();
#pragma unroll
    for (int ms = 0; ms < 2; ms++) {
        int lr = wrow * 32 + ms * 16 + g;
        int m0 = mtile + lr, m8 = m0 + 8;
        float inv0 = 1.0f / fmaxf(sqrtf(s_ssq[lr][0] + s_ssq[lr][1]), 1e-12f);
        float inv8 = 1.0f / fmaxf(sqrtf(s_ssq[lr + 8][0] + s_ssq[lr + 8][1]), 1e-12f);
        float pp0 = 0.f, pp8 = 0.f;
#pragma unroll
        for (int nt = 0; nt < 8; nt++) {
            int col = wcol * 64 + nt * 8 + tig * 2;
            float e0 = acc[ms][nt][0] * inv0;
            float e1 = acc[ms][nt][1] * inv0;
            float e2 = acc[ms][nt][2] * inv8;
            float e3 = acc[ms][nt][3] * inv8;
            if (LAYER == 1) {
                e0 = fmaxf(e0, 0.f); e1 = fmaxf(e1, 0.f);
                e2 = fmaxf(e2, 0.f); e3 = fmaxf(e3, 0.f);
                if (m0 < n) h16out[(size_t)m0 * 64 + (col >> 1)] = pack2h(e0, e1);
                if (m8 < n) h16out[(size_t)m8 * 64 + (col >> 1)] = pack2h(e2, e3);
                float a0 = (m0 < n) ? e0 : 0.f;
                float a1 = (m0 < n) ? e1 : 0.f;
                float a2 = (m8 < n) ? e2 : 0.f;
                float a3 = (m8 < n) ? e3 : 0.f;
                float sc0 = a0 + a2, sc1 = a1 + a3;
                float qc0 = a0 * a0 + a2 * a2, qc1 = a1 * a1 + a3 * a3;
#pragma unroll
                for (int o = 4; o < 32; o <<= 1) {
                    sc0 += __shfl_xor_sync(0xffffffffu, sc0, o);
                    sc1 += __shfl_xor_sync(0xffffffffu, sc1, o);
                    qc0 += __shfl_xor_sync(0xffffffffu, qc0, o);
                    qc1 += __shfl_xor_sync(0xffffffffu, qc1, o);
                }
                if (g == 0) {
                    atomicAdd(&bnS[col], sc0);
                    atomicAdd(&bnS[col + 1], sc1);
                    atomicAdd(&bnQ[col], qc0);
                    atomicAdd(&bnQ[col + 1], qc1);
                }
            } else {
                if (m0 < n) *(float2*)(embout + (size_t)m0 * HIDD + col) =
                    make_float2(e0, e1);
                if (m8 < n) *(float2*)(embout + (size_t)m8 * HIDD + col) =
                    make_float2(e2, e3);
                if (wcol == 0) {
                    pp0 += e0 * s_fcw[col] + e1 * s_fcw[col + 1];
                    pp8 += e2 * s_fcw[col] + e3 * s_fcw[col + 1];
                }
            }
        }
        if (LAYER == 2 && wcol == 0) {
            pp0 += __shfl_xor_sync(0xffffffffu, pp0, 1);
            pp0 += __shfl_xor_sync(0xffffffffu, pp0, 2);
            pp8 += __shfl_xor_sync(0xffffffffu, pp8, 1);
            pp8 += __shfl_xor_sync(0xffffffffu, pp8, 2);
            if (tig == 0) {
                float fb0 = fcb[0];
                if (m0 < n) predout[m0] = pp0 + fb0;
                if (m8 < n) predout[m8] = pp8 + fb0;
            }
        }
    }
    if (LAYER == 1) {
        __syncthreads();
        if (t < 128) {
            atomicAdd(&g_bnsum[t], bnS[t]);
            atomicAdd(&g_bnss[t], bnQ[t]);
        }
    }
}

// ---------------- launch ----------------------------------------------------
extern "C" void kernel_launch(void* const* d_in, const int* in_sizes, int n_in,
                              void* d_out, int out_size) {
    const float* x = (const float*)d_in[0];
    const int* ei = (const int*)d_in[1];
    const float* W1l = (const float*)d_in[2];
    const float* b1l = (const float*)d_in[3];
    const float* W1r = (const float*)d_in[4];
    const float* gamma = (const float*)d_in[5];
    const float* beta = (const float*)d_in[6];
    const float* W2l = (const float*)d_in[7];
    const float* b2l = (const float*)d_in[8];
    const float* W2r = (const float*)d_in[9];
    const float* fcW = (const float*)d_in[10];
    const float* fcb = (const float*)d_in[11];

    const int n = in_sizes[0] / HIDD;
    const int E = in_sizes[1] / 2;
    const int* src = ei;
    const int* dst = ei + E;

    float* preds = (float*)d_out;
    float* embed = (float*)d_out + n;

    uint32_t* gxh;    cudaGetSymbolAddress((void**)&gxh, g_xh);
    uint32_t* gh0h;   cudaGetSymbolAddress((void**)&gh0h, g_h0h);
    uint32_t* gmeanh; cudaGetSymbolAddress((void**)&gmeanh, g_meanh);
    float* gbias2;    cudaGetSymbolAddress((void**)&gbias2, g_bias2);

    const int nb = (n + 1023) / 1024;
    const int gemmg = (n + 127) / 128;

    k_hist<<<(E + 255) / 256, 256>>>(dst, E);
    k_scan1<<<nb, 1024>>>(n);
    k_scan3<<<(n + 255) / 256, 256>>>(n, E, nb);
    k_fill<<<(E + 255) / 256, 256>>>(src, dst, E);
    k_cvtx<<<(n * 32 + 255) / 256, 256>>>(x, n);
    k_prepw<<<64, 256>>>(W1l, W1r, 0, 0);

    // layer 1
    k_agg<<<(n + 7) / 8, 256>>>(gxh, n, 0);
    k_mma<1><<<gemmg, 256>>>(gmeanh, gxh, b1l, nullptr, nullptr, gh0h,
                             nullptr, nullptr, n);
    k_bnfin<<<1, 128>>>(gamma, beta, b2l, W2r, n);
    k_prepw<<<64, 256>>>(W2l, W2r, 1, 1);

    // layer 2
    k_agg<<<(n + 7) / 8, 256>>>(gh0h, n, 1);
    k_mma<2><<<gemmg, 256>>>(gmeanh, gh0h, gbias2, fcW, fcb, nullptr,
                             embed, preds, n);
}

// round 15
// speedup vs baseline: 1.3979x; 1.0054x over previous
#include <cuda_runtime.h>
#include <math.h>
#include <stdint.h>

#define HIDD 128
#define NMAX 100352
#define EMAX 602112

// ---------------- scratch (device globals; no allocation allowed) ----------
// g_cnt, g_bnsum, g_bnss rely on static zero-init; every kernel_launch call
// restores them to zero after use (scan3 / bnfin), so "zero at entry" holds
// across graph replays.
__device__ int   g_cnt[NMAX];
__device__ int   g_incl[NMAX];
__device__ int   g_bsum[256];
__device__ int   g_rowptr[NMAX + 1];
__device__ int   g_wpos[NMAX];
__device__ int   g_csr[EMAX];
__device__ uint32_t g_xh[(size_t)NMAX * 64];     // x as fp16x2
__device__ uint32_t g_h0h[(size_t)NMAX * 64];    // h0 as fp16x2
__device__ uint32_t g_meanh[(size_t)NMAX * 64];  // mean as fp16x2
__device__ float g_bnsum[HIDD];
__device__ float g_bnss[HIDD];
__device__ float g_scale[HIDD];
__device__ float g_shift[HIDD];
// B fragments (fp16x2): [layer][ (chunk16*16+ntile)*2+part ][64]
__device__ uint32_t g_Bfrag[2][16 * 16 * 2 * 64];
__device__ float g_bias2[HIDD];

// ---------------- helpers ---------------------------------------------------
__device__ __forceinline__ float f16rd(float x) {
    float r;
    asm("{.reg .b16 t; cvt.rn.f16.f32 t, %1; cvt.f32.f16 %0, t;}"
        : "=f"(r) : "f"(x));
    return r;
}
// pack: e0 -> low 16 bits, e1 -> high 16 bits (PTX: first src = upper half)
__device__ __forceinline__ uint32_t pack2h(float e0, float e1) {
    uint32_t r;
    asm("cvt.rn.f16x2.f32 %0, %1, %2;" : "=r"(r) : "f"(e1), "f"(e0));
    return r;
}
__device__ __forceinline__ float2 h2f(uint32_t u) {
    float2 r;
    asm("{.reg .b16 lo,hi; mov.b32 {lo,hi}, %2; cvt.f32.f16 %0, lo; cvt.f32.f16 %1, hi;}"
        : "=f"(r.x), "=f"(r.y) : "r"(u));
    return r;
}
__device__ __forceinline__ uint32_t smem_u32(const void* p) {
    uint32_t a;
    asm("{ .reg .u64 t; cvta.to.shared.u64 t, %1; cvt.u32.u64 %0, t; }"
        : "=r"(a) : "l"(p));
    return a;
}
__device__ __forceinline__ void ldm4(uint32_t* r, uint32_t addr) {
    asm volatile(
        "ldmatrix.sync.aligned.m8n8.x4.shared.b16 {%0,%1,%2,%3}, [%4];"
        : "=r"(r[0]), "=r"(r[1]), "=r"(r[2]), "=r"(r[3]) : "r"(addr));
}
__device__ __forceinline__ void mma16(float* c, const uint32_t* a, uint32_t b0,
                                      uint32_t b1) {
    asm volatile(
        "mma.sync.aligned.m16n8k16.row.col.f32.f16.f16.f32 "
        "{%0,%1,%2,%3},{%4,%5,%6,%7},{%8,%9},{%0,%1,%2,%3};"
        : "+f"(c[0]), "+f"(c[1]), "+f"(c[2]), "+f"(c[3])
        : "r"(a[0]), "r"(a[1]), "r"(a[2]), "r"(a[3]), "r"(b0), "r"(b1));
}

// ---------------- setup kernels ---------------------------------------------
__global__ void k_hist(const int* __restrict__ dst, int E) {
    int e = blockIdx.x * blockDim.x + threadIdx.x;
    if (e < E) atomicAdd(&g_cnt[dst[e]], 1);
}
__global__ void k_scan1(int n) {
    __shared__ int s[1024];
    int t = threadIdx.x;
    int i = blockIdx.x * 1024 + t;
    int v = (i < n) ? g_cnt[i] : 0;
    s[t] = v;
    __syncthreads();
    for (int off = 1; off < 1024; off <<= 1) {
        int x = (t >= off) ? s[t - off] : 0;
        __syncthreads();
        s[t] += x;
        __syncthreads();
    }
    if (i < n) g_incl[i] = s[t];
    if (t == 1023) g_bsum[blockIdx.x] = s[1023];
}
// scan2+scan3 fused; re-zeroes g_cnt for next call.
__global__ void k_scan3(int n, int E, int nb) {
    __shared__ int sb[128];
    int t = threadIdx.x;  // 256 threads
    if (t < 128) sb[t] = (t < nb) ? g_bsum[t] : 0;
    __syncthreads();
    for (int off = 1; off < 128; off <<= 1) {
        int x = 0;
        if (t < 128 && t >= off) x = sb[t - off];
        __syncthreads();
        if (t < 128) sb[t] += x;
        __syncthreads();
    }
    int i = blockIdx.x * blockDim.x + t;
    if (i < n) {
        int blk = i >> 10;
        int boff = (blk == 0) ? 0 : sb[blk - 1];
        int excl = g_incl[i] - g_cnt[i] + boff;
        g_rowptr[i] = excl;
        g_wpos[i] = excl;
        g_cnt[i] = 0;
        if (i == 0) g_rowptr[n] = E;
    }
}
__global__ void k_fill(const int* __restrict__ src, const int* __restrict__ dst, int E) {
    int e = blockIdx.x * blockDim.x + threadIdx.x;
    if (e < E) {
        int d = dst[e];
        int p = atomicAdd(&g_wpos[d], 1);
        g_csr[p] = src[e];
    }
}
// x -> fp16x2
__global__ void k_cvtx(const float* __restrict__ x, int n) {
    int i = blockIdx.x * 256 + threadIdx.x;  // n*32 total
    if (i < n * 32) {
        float4 v = ((const float4*)x)[i];
        uint2 o;
        o.x = pack2h(v.x, v.y);
        o.y = pack2h(v.z, v.w);
        ((uint2*)g_xh)[i] = o;
    }
}

// weight -> fp16 hi/lo b-fragments for m16n8k16 row.col
__global__ void k_prepw(const float* __restrict__ Wl, const float* __restrict__ Wr,
                        int layer, int useScale) {
    int idx = blockIdx.x * 256 + threadIdx.x;  // 16384 total
    int reg = idx & 1;
    int lane = (idx >> 1) & 31;
    int ntile = (idx >> 6) & 15;
    int chunk = idx >> 10;
    int tig = lane & 3, gcol = lane >> 2;
    int nn = ntile * 8 + gcol;
    int k0 = chunk * 16 + reg * 8 + tig * 2;
    int k1 = k0 + 1;
    float w0 = (k0 < HIDD) ? Wl[k0 * HIDD + nn] : Wr[(k0 - HIDD) * HIDD + nn];
    float w1 = (k1 < HIDD) ? Wl[k1 * HIDD + nn] : Wr[(k1 - HIDD) * HIDD + nn];
    if (useScale && k0 >= HIDD) {
        w0 *= g_scale[k0 - HIDD];
        w1 *= g_scale[k1 - HIDD];
    }
    float h0 = f16rd(w0), h1 = f16rd(w1);
    int base = ((chunk * 16 + ntile) * 2) * 64 + lane * 2 + reg;
    g_Bfrag[layer][base] = pack2h(w0, w1);
    g_Bfrag[layer][base + 64] = pack2h(w0 - h0, w1 - h1);
}

// BN finalize + bias2 fused. Re-zeroes g_bnsum/g_bnss.
__global__ void k_bnfin(const float* __restrict__ gamma, const float* __restrict__ beta,
                        const float* __restrict__ b2l, const float* __restrict__ W2r,
                        int n) {
    __shared__ float sh[HIDD];
    int c = threadIdx.x;  // 128 threads
    float mu = g_bnsum[c] / (float)n;
    float var = g_bnss[c] / (float)n - mu * mu;
    float sc = gamma[c] * rsqrtf(var + 1e-5f);
    float shf = beta[c] - mu * sc;
    g_scale[c] = sc;
    g_shift[c] = shf;
    sh[c] = shf;
    g_bnsum[c] = 0.f;
    g_bnss[c] = 0.f;
    __syncthreads();
    float s = b2l[c];
    for (int j = 0; j < HIDD; j++) s += sh[j] * W2r[j * HIDD + c];
    g_bias2[c] = s;
}

// ---------------- aggregation: half-warp per node ---------------------------
// Lanes 0-15 gather node base+0, lanes 16-31 gather node base+1 — same
// instruction stream (no divergence), per-lane bound predicates, loop trip =
// warp-max degree. Each lane owns 8 features (one uint4 of fp16x2).
// Per-feature edge summation order is identical to the warp-per-node version.
__global__ void k_agg(const uint32_t* __restrict__ feat, int n, int layer2) {
    int gw = (blockIdx.x * blockDim.x + threadIdx.x) >> 5;
    int lane = threadIdx.x & 31;
    int grp = lane >> 4;
    int ln = lane & 15;
    int node = gw * 2 + grp;
    bool valid = node < n;
    int r0 = 0, r1 = 0;
    if (valid) {
        r0 = g_rowptr[node];
        r1 = g_rowptr[node + 1];
    }
    int deg = r1 - r0;
    int mx = deg;
#pragma unroll
    for (int o = 16; o; o >>= 1) mx = max(mx, __shfl_xor_sync(0xffffffffu, mx, o));
    if (mx == 0 && !valid) return;

    const uint4* f4 = (const uint4*)feat;  // row = 16 uint4
    float a[8] = {0.f, 0.f, 0.f, 0.f, 0.f, 0.f, 0.f, 0.f};

    int j = 0;
    for (; j + 3 < mx; j += 4) {
        uint4 v[4];
#pragma unroll
        for (int e = 0; e < 4; e++) {
            int idx = r0 + j + e;
            v[e] = (idx < r1) ? f4[(size_t)g_csr[idx] * 16 + ln]
                              : make_uint4(0u, 0u, 0u, 0u);
        }
#pragma unroll
        for (int e = 0; e < 4; e++) {
            float2 p;
            p = h2f(v[e].x); a[0] += p.x; a[1] += p.y;
            p = h2f(v[e].y); a[2] += p.x; a[3] += p.y;
            p = h2f(v[e].z); a[4] += p.x; a[5] += p.y;
            p = h2f(v[e].w); a[6] += p.x; a[7] += p.y;
        }
    }
    for (; j < mx; j++) {
        int idx = r0 + j;
        if (idx < r1) {
            uint4 v = f4[(size_t)g_csr[idx] * 16 + ln];
            float2 p;
            p = h2f(v.x); a[0] += p.x; a[1] += p.y;
            p = h2f(v.y); a[2] += p.x; a[3] += p.y;
            p = h2f(v.z); a[4] += p.x; a[5] += p.y;
            p = h2f(v.w); a[6] += p.x; a[7] += p.y;
        }
    }

    float inv = (deg > 0) ? 1.f / (float)deg : 0.f;
#pragma unroll
    for (int i = 0; i < 8; i++) a[i] *= inv;
    if (layer2) {
        if (deg > 0) {
            float4 sc0 = *(const float4*)(g_scale + ln * 8);
            float4 sc1 = *(const float4*)(g_scale + ln * 8 + 4);
            float4 sh0 = *(const float4*)(g_shift + ln * 8);
            float4 sh1 = *(const float4*)(g_shift + ln * 8 + 4);
            a[0] = a[0] * sc0.x + sh0.x; a[1] = a[1] * sc0.y + sh0.y;
            a[2] = a[2] * sc0.z + sh0.z; a[3] = a[3] * sc0.w + sh0.w;
            a[4] = a[4] * sc1.x + sh1.x; a[5] = a[5] * sc1.y + sh1.y;
            a[6] = a[6] * sc1.z + sh1.z; a[7] = a[7] * sc1.w + sh1.w;
        } else {
#pragma unroll
            for (int i = 0; i < 8; i++) a[i] = 0.f;
        }
    }
    if (valid) {
        uint4 o;
        o.x = pack2h(a[0], a[1]);
        o.y = pack2h(a[2], a[3]);
        o.z = pack2h(a[4], a[5]);
        o.w = pack2h(a[6], a[7]);
        ((uint4*)g_meanh)[(size_t)node * 16 + ln] = o;
    }
}

// ---------------- GEMM via fp16 m16n8k16 mma (A single, B hi+lo) ------------
// Block: 128 rows x 128 cols x K=256, 256 threads = 8 warps (4 mrow x 2 ncol).
// A operands are pre-quantized fp16x2 in gmem -> staging is a pure uint4 copy.
// LAYER 1: writes h0 as fp16x2 + BN column sums. LAYER 2: embed fp32 + preds.
template <int LAYER>
__global__ __launch_bounds__(256, 2) void k_mma(
    const uint32_t* __restrict__ meanbuf, const uint32_t* __restrict__ featbuf,
    const float* __restrict__ bias, const float* __restrict__ fcW,
    const float* __restrict__ fcb, uint32_t* __restrict__ h16out,
    float* __restrict__ embout, float* __restrict__ predout, int n) {
    __shared__ __align__(16) uint32_t sA[2][128 * 12];  // [buf][row*12+pair]
    __shared__ float s_bias[128];
    __shared__ float s_fcw[64];
    __shared__ float s_ssq[128][2];
    __shared__ float bnS[128];
    __shared__ float bnQ[128];

    const int t = threadIdx.x;
    const int wid = t >> 5, lane = t & 31;
    const int wrow = wid >> 1, wcol = wid & 1;
    const int mtile = blockIdx.x * 128;

    if (t < 128) {
        s_bias[t] = bias[t];
        if (LAYER == 1) { bnS[t] = 0.f; bnQ[t] = 0.f; }
    }
    if (LAYER == 2 && t < 64) s_fcw[t] = fcW[t];

    float acc[2][8][4];
#pragma unroll
    for (int ms = 0; ms < 2; ms++)
#pragma unroll
        for (int nt = 0; nt < 8; nt++)
#pragma unroll
            for (int j = 0; j < 4; j++) acc[ms][nt][j] = 0.f;

    const uint32_t* __restrict__ Bf = g_Bfrag[LAYER - 1];

    const int srow = t >> 1;       // staged row (0..127)
    const int kh = t & 1;          // k half -> 4 uint32 (8 halves)
    const uint32_t sAb = smem_u32(&sA[0][0]);
    const int lrow = lane & 15;
    const int kpair = (lane >> 4) * 4;
    const int m_st = mtile + srow;
    const bool mok = (m_st < n);

    // prefetch chunk 0
    uint4 av = make_uint4(0u, 0u, 0u, 0u);
    if (mok) av = *(const uint4*)(meanbuf + (size_t)m_st * 64 + kh * 4);

    for (int chunk = 0; chunk < 16; chunk++) {
        const int buf = chunk & 1;
        // ---- stage A chunk: pure copy ----
        *(uint4*)&sA[buf][srow * 12 + kh * 4] = av;
        __syncthreads();
        // ---- prefetch next chunk ----
        if (chunk < 15) {
            int c1 = chunk + 1;
            const uint32_t* src = (c1 < 8) ? meanbuf : featbuf;
            int kc = (c1 & 7) * 8 + kh * 4;
            av = mok ? *(const uint4*)(src + (size_t)m_st * 64 + kc)
                     : make_uint4(0u, 0u, 0u, 0u);
        }
        // ---- A fragments via ldmatrix ----
        uint32_t Ah[2][4];
#pragma unroll
        for (int ms = 0; ms < 2; ms++) {
            int r = wrow * 32 + ms * 16 + lrow;
            uint32_t off = (uint32_t)(r * 12 + kpair) * 4u;
            ldm4(Ah[ms], sAb + buf * 6144u + off);
        }
        // ---- B hi fragments ----
        uint32_t Bh[8][2];
#pragma unroll
        for (int nt = 0; nt < 8; nt++) {
            const uint32_t* bp =
                Bf + ((size_t)(chunk * 16 + wcol * 8 + nt) * 2) * 64 + lane * 2;
            Bh[nt][0] = bp[0];
            Bh[nt][1] = bp[1];
        }
#pragma unroll
        for (int ms = 0; ms < 2; ms++)
#pragma unroll
            for (int nt = 0; nt < 8; nt++)
                mma16(acc[ms][nt], Ah[ms], Bh[nt][0], Bh[nt][1]);
        // ---- B lo fragments ----
#pragma unroll
        for (int nt = 0; nt < 8; nt++) {
            const uint32_t* bp =
                Bf + ((size_t)(chunk * 16 + wcol * 8 + nt) * 2 + 1) * 64 + lane * 2;
            Bh[nt][0] = bp[0];
            Bh[nt][1] = bp[1];
        }
#pragma unroll
        for (int ms = 0; ms < 2; ms++)
#pragma unroll
            for (int nt = 0; nt < 8; nt++)
                mma16(acc[ms][nt], Ah[ms], Bh[nt][0], Bh[nt][1]);
    }

    // ---- epilogue ----
    const int g = lane >> 2, tig = lane & 3;
#pragma unroll
    for (int ms = 0; ms < 2; ms++) {
        float ss0 = 0.f, ss8 = 0.f;
#pragma unroll
        for (int nt = 0; nt < 8; nt++) {
            int col = wcol * 64 + nt * 8 + tig * 2;
            acc[ms][nt][0] += s_bias[col];
            acc[ms][nt][1] += s_bias[col + 1];
            acc[ms][nt][2] += s_bias[col];
            acc[ms][nt][3] += s_bias[col + 1];
            ss0 += acc[ms][nt][0] * acc[ms][nt][0] + acc[ms][nt][1] * acc[ms][nt][1];
            ss8 += acc[ms][nt][2] * acc[ms][nt][2] + acc[ms][nt][3] * acc[ms][nt][3];
        }
        ss0 += __shfl_xor_sync(0xffffffffu, ss0, 1);
        ss0 += __shfl_xor_sync(0xffffffffu, ss0, 2);
        ss8 += __shfl_xor_sync(0xffffffffu, ss8, 1);
        ss8 += __shfl_xor_sync(0xffffffffu, ss8, 2);
        if (tig == 0) {
            s_ssq[wrow * 32 + ms * 16 + g][wcol] = ss0;
            s_ssq[wrow * 32 + ms * 16 + g + 8][wcol] = ss8;
        }
    }
    __syncthreads();
#pragma unroll
    for (int ms = 0; ms < 2; ms++) {
        int lr = wrow * 32 + ms * 16 + g;
        int m0 = mtile + lr, m8 = m0 + 8;
        float inv0 = 1.0f / fmaxf(sqrtf(s_ssq[lr][0] + s_ssq[lr][1]), 1e-12f);
        float inv8 = 1.0f / fmaxf(sqrtf(s_ssq[lr + 8][0] + s_ssq[lr + 8][1]), 1e-12f);
        float pp0 = 0.f, pp8 = 0.f;
#pragma unroll
        for (int nt = 0; nt < 8; nt++) {
            int col = wcol * 64 + nt * 8 + tig * 2;
            float e0 = acc[ms][nt][0] * inv0;
            float e1 = acc[ms][nt][1] * inv0;
            float e2 = acc[ms][nt][2] * inv8;
            float e3 = acc[ms][nt][3] * inv8;
            if (LAYER == 1) {
                e0 = fmaxf(e0, 0.f); e1 = fmaxf(e1, 0.f);
                e2 = fmaxf(e2, 0.f); e3 = fmaxf(e3, 0.f);
                if (m0 < n) h16out[(size_t)m0 * 64 + (col >> 1)] = pack2h(e0, e1);
                if (m8 < n) h16out[(size_t)m8 * 64 + (col >> 1)] = pack2h(e2, e3);
                float a0 = (m0 < n) ? e0 : 0.f;
                float a1 = (m0 < n) ? e1 : 0.f;
                float a2 = (m8 < n) ? e2 : 0.f;
                float a3 = (m8 < n) ? e3 : 0.f;
                float sc0 = a0 + a2, sc1 = a1 + a3;
                float qc0 = a0 * a0 + a2 * a2, qc1 = a1 * a1 + a3 * a3;
#pragma unroll
                for (int o = 4; o < 32; o <<= 1) {
                    sc0 += __shfl_xor_sync(0xffffffffu, sc0, o);
                    sc1 += __shfl_xor_sync(0xffffffffu, sc1, o);
                    qc0 += __shfl_xor_sync(0xffffffffu, qc0, o);
                    qc1 += __shfl_xor_sync(0xffffffffu, qc1, o);
                }
                if (g == 0) {
                    atomicAdd(&bnS[col], sc0);
                    atomicAdd(&bnS[col + 1], sc1);
                    atomicAdd(&bnQ[col], qc0);
                    atomicAdd(&bnQ[col + 1], qc1);
                }
            } else {
                if (m0 < n) *(float2*)(embout + (size_t)m0 * HIDD + col) =
                    make_float2(e0, e1);
                if (m8 < n) *(float2*)(embout + (size_t)m8 * HIDD + col) =
                    make_float2(e2, e3);
                if (wcol == 0) {
                    pp0 += e0 * s_fcw[col] + e1 * s_fcw[col + 1];
                    pp8 += e2 * s_fcw[col] + e3 * s_fcw[col + 1];
                }
            }
        }
        if (LAYER == 2 && wcol == 0) {
            pp0 += __shfl_xor_sync(0xffffffffu, pp0, 1);
            pp0 += __shfl_xor_sync(0xffffffffu, pp0, 2);
            pp8 += __shfl_xor_sync(0xffffffffu, pp8, 1);
            pp8 += __shfl_xor_sync(0xffffffffu, pp8, 2);
            if (tig == 0) {
                float fb0 = fcb[0];
                if (m0 < n) predout[m0] = pp0 + fb0;
                if (m8 < n) predout[m8] = pp8 + fb0;
            }
        }
    }
    if (LAYER == 1) {
        __syncthreads();
        if (t < 128) {
            atomicAdd(&g_bnsum[t], bnS[t]);
            atomicAdd(&g_bnss[t], bnQ[t]);
        }
    }
}

// ---------------- launch ----------------------------------------------------
extern "C" void kernel_launch(void* const* d_in, const int* in_sizes, int n_in,
                              void* d_out, int out_size) {
    const float* x = (const float*)d_in[0];
    const int* ei = (const int*)d_in[1];
    const float* W1l = (const float*)d_in[2];
    const float* b1l = (const float*)d_in[3];
    const float* W1r = (const float*)d_in[4];
    const float* gamma = (const float*)d_in[5];
    const float* beta = (const float*)d_in[6];
    const float* W2l = (const float*)d_in[7];
    const float* b2l = (const float*)d_in[8];
    const float* W2r = (const float*)d_in[9];
    const float* fcW = (const float*)d_in[10];
    const float* fcb = (const float*)d_in[11];

    const int n = in_sizes[0] / HIDD;
    const int E = in_sizes[1] / 2;
    const int* src = ei;
    const int* dst = ei + E;

    float* preds = (float*)d_out;
    float* embed = (float*)d_out + n;

    uint32_t* gxh;    cudaGetSymbolAddress((void**)&gxh, g_xh);
    uint32_t* gh0h;   cudaGetSymbolAddress((void**)&gh0h, g_h0h);
    uint32_t* gmeanh; cudaGetSymbolAddress((void**)&gmeanh, g_meanh);
    float* gbias2;    cudaGetSymbolAddress((void**)&gbias2, g_bias2);

    const int nb = (n + 1023) / 1024;
    const int gemmg = (n + 127) / 128;
    const int aggg = (n + 15) / 16;  // 8 warps/block, 2 nodes/warp

    k_hist<<<(E + 255) / 256, 256>>>(dst, E);
    k_scan1<<<nb, 1024>>>(n);
    k_scan3<<<(n + 255) / 256, 256>>>(n, E, nb);
    k_fill<<<(E + 255) / 256, 256>>>(src, dst, E);
    k_cvtx<<<(n * 32 + 255) / 256, 256>>>(x, n);
    k_prepw<<<64, 256>>>(W1l, W1r, 0, 0);

    // layer 1
    k_agg<<<aggg, 256>>>(gxh, n, 0);
    k_mma<1><<<gemmg, 256>>>(gmeanh, gxh, b1l, nullptr, nullptr, gh0h,
                             nullptr, nullptr, n);
    k_bnfin<<<1, 128>>>(gamma, beta, b2l, W2r, n);
    k_prepw<<<64, 256>>>(W2l, W2r, 1, 1);

    // layer 2
    k_agg<<<aggg, 256>>>(gh0h, n, 1);
    k_mma<2><<<gemmg, 256>>>(gmeanh, gh0h, gbias2, fcW, fcb, nullptr,
                             embed, preds, n);
}